// round 11
// baseline (speedup 1.0000x reference)
#include <cuda_runtime.h>
#include <cuda_bf16.h>
#include <cstdint>
#include <cstddef>

#define B_N   16384
#define F_D   512
#define H_D   256
#define NLOC  12

// ---------------- device scratch ----------------
__device__ float         DU  [B_N * F_D];        // u = g@M1 + c_u (fp32, for k_mid)
__device__ float         DLFM[B_N * F_D];        // lf_mean + b_dr
__device__ __nv_bfloat16 GH[B_N * F_D], GL[B_N * F_D];    // g split
__device__ __nv_bfloat16 DPH[B_N * F_D], DPL[B_N * F_D];  // p split
__device__ __nv_bfloat16 M1TH[F_D * F_D], M1TL[F_D * F_D];        // (Wq@Wk^T)^T : [n][k]
__device__ __nv_bfloat16 W2TH[F_D * 2 * F_D], W2TL[F_D * 2 * F_D];// W2^T : [n][k]
__device__ float DCU [F_D];
__device__ float DCZ [F_D];
__device__ float DSWB[2];                        // [0]=sum(w_dr), [1]=b_dr

// ---------------- PTX helpers ----------------
__device__ __forceinline__ void cpa16(unsigned int s, const void* g) {
    asm volatile("cp.async.cg.shared.global [%0], [%1], 16;\n" :: "r"(s), "l"(g));
}
__device__ __forceinline__ void cpa_commit() { asm volatile("cp.async.commit_group;\n"); }
__device__ __forceinline__ void cpa_wait0()  { asm volatile("cp.async.wait_group 0;\n"); }
__device__ __forceinline__ void cpa_wait1()  { asm volatile("cp.async.wait_group 1;\n"); }
__device__ __forceinline__ void cpa_wait2()  { asm volatile("cp.async.wait_group 2;\n"); }

__device__ __forceinline__ void mma_bf16(float* c, uint32_t a0, uint32_t a1, uint32_t a2,
                                         uint32_t a3, uint32_t b0, uint32_t b1) {
    asm volatile(
        "mma.sync.aligned.m16n8k16.row.col.f32.bf16.bf16.f32 "
        "{%0,%1,%2,%3}, {%4,%5,%6,%7}, {%8,%9}, {%0,%1,%2,%3};\n"
        : "+f"(c[0]), "+f"(c[1]), "+f"(c[2]), "+f"(c[3])
        : "r"(a0), "r"(a1), "r"(a2), "r"(a3), "r"(b0), "r"(b1));
}

__device__ __forceinline__ void split_bf16(float x, __nv_bfloat16& h, __nv_bfloat16& l) {
    h = __float2bfloat16(x);
    l = __float2bfloat16(x - __bfloat162float(h));
}

// ---------------- kernel 0: scalars ----------------
__global__ void k_sw(const float* __restrict__ w_dr, const float* __restrict__ b_dr) {
    if (threadIdx.x == 0) {
        float s = 0.f;
        for (int k = 0; k < NLOC; ++k) s += w_dr[k];
        DSWB[0] = s;
        DSWB[1] = b_dr[0];
    }
}

// ---------------- kernel 1: weight prep -> transposed bf16 hi/lo ----------------
// mat 0: M1T[n][k]        = sum_h Wq[k][h] * Wk[n][h]
// mat 1: W2T[n][k], k<512 = Sw * sum_h Wv[k][h] * Wf[256+h][n]   (multiplies g)
// mat 2: W2T[n][512+k]    =      sum_h Wv[k][h] * Wf[h][n]       (multiplies p)
__global__ __launch_bounds__(256) void k_prep(const float* __restrict__ Wq,
                                              const float* __restrict__ Wk,
                                              const float* __restrict__ Wv,
                                              const float* __restrict__ Wf) {
    __shared__ float As[16][68];
    __shared__ float Bs[16][68];
    const int tid = threadIdx.x;
    const int tx = tid & 15, ty = tid >> 4;
    const int m0 = blockIdx.y * 64, n0 = blockIdx.x * 64, mat = blockIdx.z;
    const float* A = (mat == 0) ? Wq : Wv;
    float acc[4][4];
    #pragma unroll
    for (int i = 0; i < 4; ++i)
        #pragma unroll
        for (int j = 0; j < 4; ++j) acc[i][j] = 0.f;

    for (int kk = 0; kk < 256; kk += 16) {
        {
            int m = tid >> 2, kq = (tid & 3) * 4;
            float4 v = *(const float4*)&A[(m0 + m) * 256 + kk + kq];
            As[kq + 0][m] = v.x; As[kq + 1][m] = v.y; As[kq + 2][m] = v.z; As[kq + 3][m] = v.w;
        }
        if (mat == 0) {
            int n = tid >> 2, kq = (tid & 3) * 4;
            float4 v = *(const float4*)&Wk[(n0 + n) * 256 + kk + kq];
            Bs[kq + 0][n] = v.x; Bs[kq + 1][n] = v.y; Bs[kq + 2][n] = v.z; Bs[kq + 3][n] = v.w;
        } else {
            int kr = tid >> 4, nq = (tid & 15) * 4;
            int off = (mat == 1) ? 256 : 0;
            float4 v = *(const float4*)&Wf[(off + kk + kr) * 512 + n0 + nq];
            *(float4*)&Bs[kr][nq] = v;
        }
        __syncthreads();
        #pragma unroll
        for (int k = 0; k < 16; ++k) {
            float4 a = *(const float4*)&As[k][ty * 4];
            float4 b = *(const float4*)&Bs[k][tx * 4];
            float av[4] = {a.x, a.y, a.z, a.w};
            float bv[4] = {b.x, b.y, b.z, b.w};
            #pragma unroll
            for (int i = 0; i < 4; ++i)
                #pragma unroll
                for (int j = 0; j < 4; ++j) acc[i][j] = fmaf(av[i], bv[j], acc[i][j]);
        }
        __syncthreads();
    }
    const float sw = DSWB[0];
    #pragma unroll
    for (int i = 0; i < 4; ++i) {
        int m = m0 + ty * 4 + i;            // k index of the big GEMM
        #pragma unroll
        for (int j = 0; j < 4; ++j) {
            int n = n0 + tx * 4 + j;        // output col
            float v = acc[i][j];
            __nv_bfloat16 h, l;
            if (mat == 0) {
                split_bf16(v, h, l);
                M1TH[n * 512 + m] = h; M1TL[n * 512 + m] = l;
            } else if (mat == 1) {
                split_bf16(v * sw, h, l);
                W2TH[n * 1024 + m] = h; W2TL[n * 1024 + m] = l;
            } else {
                split_bf16(v, h, l);
                W2TH[n * 1024 + 512 + m] = h; W2TL[n * 1024 + 512 + m] = l;
            }
        }
    }
}

// ---------------- kernel 2: constant vectors ----------------
__global__ void k_const(const float* __restrict__ bq, const float* __restrict__ Wk,
                        const float* __restrict__ bv, const float* __restrict__ Wf,
                        const float* __restrict__ bf) {
    const int o = threadIdx.x;   // 512 threads
    const float sw = DSWB[0], bdr = DSWB[1];
    float cu = 0.f;
    for (int h = 0; h < 256; ++h) cu = fmaf(bq[h], Wk[o * 256 + h], cu);
    DCU[o] = cu;
    float cz = bf[o];
    for (int h = 0; h < 256; ++h) {
        cz = fmaf(bv[h], Wf[h * 512 + o], cz);
        cz = fmaf(fmaf(sw, bv[h], bdr), Wf[(256 + h) * 512 + o], cz);
    }
    DCZ[o] = cz;
}

// ---------------- kernel 3: split g -> bf16 hi/lo ----------------
__global__ __launch_bounds__(256) void k_cvt_g(const float* __restrict__ g) {
    const size_t i = (size_t)blockIdx.x * 256 + threadIdx.x;   // float4 index
    float4 v = *(const float4*)&g[i * 4];
    __nv_bfloat16 h0, l0, h1, l1, h2, l2, h3, l3;
    split_bf16(v.x, h0, l0); split_bf16(v.y, h1, l1);
    split_bf16(v.z, h2, l2); split_bf16(v.w, h3, l3);
    __nv_bfloat162* ph = (__nv_bfloat162*)GH;
    __nv_bfloat162* pl = (__nv_bfloat162*)GL;
    ph[i * 2]     = __nv_bfloat162(h0, h1);
    ph[i * 2 + 1] = __nv_bfloat162(h2, h3);
    pl[i * 2]     = __nv_bfloat162(l0, l1);
    pl[i * 2 + 1] = __nv_bfloat162(l2, l3);
}

// ---------------- warp-MMA bf16-split GEMM, 4-stage cp.async ring ----------------
// D[m][n] = sum_k A[m][k]*BT[n][k];  CTA 128x128, 8 warps (2x4), warp 64x32.
// KB=512:  A = G split, BT = M1T;  MODE 0: DU = D + DCU
// KB=1024: A = [G|P] split, BT = W2T; MODE 1: out = relu(D+DCZ)+DLFM+g
#define KC      32
#define SP      40                        // smem row stride (bf16 elems): 80B, conflict-free
#define SPLIT_E (128 * SP)                // 5120 elems per split per stage
#define STAGE_E (4 * SPLIT_E)             // Ah|Al|Bh|Bl
#define STAGES  4
#define DYN_BYTES (STAGES * STAGE_E * 2)  // 163840

template<int KB, int MODE>
__global__ __launch_bounds__(256, 1) void k_mma(const float* __restrict__ G,
                                                float* __restrict__ Out) {
    extern __shared__ __nv_bfloat16 smb[];
    const int tid    = threadIdx.x;
    const int lane   = tid & 31;
    const int wid    = tid >> 5;
    const int gid    = lane >> 2;          // group id 0..7
    const int tig    = lane & 3;           // thread in group
    const int warp_m = wid >> 2;           // 0..1
    const int warp_n = wid & 3;            // 0..3
    const int n0     = blockIdx.x * 128;
    const int row0   = blockIdx.y * 128;
    const int NC     = KB / KC;

    const __nv_bfloat16* BTH = (KB == 512) ? M1TH : W2TH;
    const __nv_bfloat16* BTL = (KB == 512) ? M1TL : W2TL;

    const uint32_t smem0 = (uint32_t)__cvta_generic_to_shared(smb);

    // load one K-chunk: Ah/Al [128 x 32] + Bh/Bl [128 x 32] (16B cp.async x 2048)
    auto load_chunk = [&](int buf, int kk) {
        const uint32_t bb = smem0 + (uint32_t)buf * (STAGE_E * 2);
        #pragma unroll
        for (int it = 0; it < 8; ++it) {
            const int q    = tid + it * 256;          // 0..2047
            const int part = q >> 9;                  // 0 Ah, 1 Al, 2 Bh, 3 Bl
            const int idx  = q & 511;
            const int row  = idx >> 2;
            const int seg  = idx & 3;                 // 16B segment (8 elems)
            const uint32_t soff = bb + (uint32_t)(part * SPLIT_E + row * SP + seg * 8) * 2;
            const __nv_bfloat16* gp;
            if (part < 2) {
                int k = kk + seg * 8;
                const __nv_bfloat16* src;
                if (KB == 1024 && k >= 512) { src = (part == 0) ? DPH : DPL; k -= 512; }
                else                        { src = (part == 0) ? GH  : GL; }
                gp = src + (size_t)(row0 + row) * 512 + k;
            } else {
                const __nv_bfloat16* src = (part == 2) ? BTH : BTL;
                gp = src + (size_t)(n0 + row) * KB + kk + seg * 8;
            }
            cpa16(soff, gp);
        }
        cpa_commit();
    };

    float acc[4][4][4];
    #pragma unroll
    for (int i = 0; i < 4; ++i)
        #pragma unroll
        for (int j = 0; j < 4; ++j)
            #pragma unroll
            for (int t = 0; t < 4; ++t) acc[i][j][t] = 0.f;

    // prefetch STAGES-1 chunks
    #pragma unroll
    for (int s = 0; s < STAGES - 1; ++s) load_chunk(s, s * KC);

    for (int c = 0; c < NC; ++c) {
        const int rem = NC - 1 - c;        // chunks after this one
        if (rem >= 2)      cpa_wait2();    // chunk c guaranteed resident
        else if (rem == 1) cpa_wait1();
        else               cpa_wait0();
        __syncthreads();                   // data visible to all; stage (c-1)&3 fully consumed
        if (c + STAGES - 1 < NC)
            load_chunk((c + STAGES - 1) & (STAGES - 1), (c + STAGES - 1) * KC);

        const __nv_bfloat16* st = smb + (c & (STAGES - 1)) * STAGE_E;
        const __nv_bfloat16* pAh = st;
        const __nv_bfloat16* pAl = st + SPLIT_E;
        const __nv_bfloat16* pBh = st + 2 * SPLIT_E;
        const __nv_bfloat16* pBl = st + 3 * SPLIT_E;

        #pragma unroll
        for (int ks = 0; ks < 2; ++ks) {
            const int kb = ks * 16;
            uint32_t ah[4][4], bh[4][2], bl[4][2];
            #pragma unroll
            for (int mt = 0; mt < 4; ++mt) {
                const int r = warp_m * 64 + mt * 16 + gid;
                ah[mt][0] = *(const uint32_t*)&pAh[(r)     * SP + kb + tig * 2];
                ah[mt][1] = *(const uint32_t*)&pAh[(r + 8) * SP + kb + tig * 2];
                ah[mt][2] = *(const uint32_t*)&pAh[(r)     * SP + kb + 8 + tig * 2];
                ah[mt][3] = *(const uint32_t*)&pAh[(r + 8) * SP + kb + 8 + tig * 2];
            }
            #pragma unroll
            for (int nt = 0; nt < 4; ++nt) {
                const int nr = warp_n * 32 + nt * 8 + gid;
                bh[nt][0] = *(const uint32_t*)&pBh[nr * SP + kb + tig * 2];
                bh[nt][1] = *(const uint32_t*)&pBh[nr * SP + kb + 8 + tig * 2];
                bl[nt][0] = *(const uint32_t*)&pBl[nr * SP + kb + tig * 2];
                bl[nt][1] = *(const uint32_t*)&pBl[nr * SP + kb + 8 + tig * 2];
            }
            #pragma unroll
            for (int mt = 0; mt < 4; ++mt)
                #pragma unroll
                for (int nt = 0; nt < 4; ++nt) {
                    mma_bf16(acc[mt][nt], ah[mt][0], ah[mt][1], ah[mt][2], ah[mt][3],
                             bh[nt][0], bh[nt][1]);
                    mma_bf16(acc[mt][nt], ah[mt][0], ah[mt][1], ah[mt][2], ah[mt][3],
                             bl[nt][0], bl[nt][1]);
                }
            uint32_t al[4][4];
            #pragma unroll
            for (int mt = 0; mt < 4; ++mt) {
                const int r = warp_m * 64 + mt * 16 + gid;
                al[mt][0] = *(const uint32_t*)&pAl[(r)     * SP + kb + tig * 2];
                al[mt][1] = *(const uint32_t*)&pAl[(r + 8) * SP + kb + tig * 2];
                al[mt][2] = *(const uint32_t*)&pAl[(r)     * SP + kb + 8 + tig * 2];
                al[mt][3] = *(const uint32_t*)&pAl[(r + 8) * SP + kb + 8 + tig * 2];
            }
            #pragma unroll
            for (int mt = 0; mt < 4; ++mt)
                #pragma unroll
                for (int nt = 0; nt < 4; ++nt)
                    mma_bf16(acc[mt][nt], al[mt][0], al[mt][1], al[mt][2], al[mt][3],
                             bh[nt][0], bh[nt][1]);
        }
    }

    // ---- epilogue ----
    #pragma unroll
    for (int mt = 0; mt < 4; ++mt) {
        #pragma unroll
        for (int nt = 0; nt < 4; ++nt) {
            const int col = n0 + warp_n * 32 + nt * 8 + tig * 2;
            #pragma unroll
            for (int half = 0; half < 2; ++half) {
                const int row = row0 + warp_m * 64 + mt * 16 + gid + half * 8;
                const float v0 = acc[mt][nt][half * 2 + 0];
                const float v1 = acc[mt][nt][half * 2 + 1];
                float2 o;
                if (MODE == 0) {
                    o.x = v0 + DCU[col];
                    o.y = v1 + DCU[col + 1];
                    *(float2*)&DU[(size_t)row * 512 + col] = o;
                } else {
                    float2 lm = *(const float2*)&DLFM[(size_t)row * 512 + col];
                    float2 g2 = *(const float2*)&G[(size_t)row * 512 + col];
                    o.x = fmaxf(v0 + DCZ[col],     0.f) + lm.x + g2.x;
                    o.y = fmaxf(v1 + DCZ[col + 1], 0.f) + lm.y + g2.y;
                    *(float2*)&Out[(size_t)row * 512 + col] = o;
                }
            }
        }
    }
}

// ---------------- middle kernel: softmax over 12 local tokens ----------------
__global__ __launch_bounds__(128) void k_mid(const float* __restrict__ lf,
                                             const float* __restrict__ w_dr) {
    __shared__ float sred[4][NLOC];
    __shared__ float swd[NLOC];
    const int b = blockIdx.x, tid = threadIdx.x;
    const int lane = tid & 31, w = tid >> 5;
    if (tid < NLOC) swd[tid] = w_dr[tid];

    float4 u4 = *(const float4*)&DU[(size_t)b * 512 + tid * 4];
    const float* base = lf + (size_t)b * NLOC * 512 + tid * 4;
    float4 lfv[NLOC];
    float part[NLOC];
    #pragma unroll
    for (int k = 0; k < NLOC; ++k) {
        lfv[k] = *(const float4*)&base[k * 512];
        part[k] = lfv[k].x * u4.x + lfv[k].y * u4.y + lfv[k].z * u4.z + lfv[k].w * u4.w;
    }
    #pragma unroll
    for (int k = 0; k < NLOC; ++k) {
        #pragma unroll
        for (int off = 16; off > 0; off >>= 1)
            part[k] += __shfl_xor_sync(0xffffffffu, part[k], off);
    }
    if (lane == 0) {
        #pragma unroll
        for (int k = 0; k < NLOC; ++k) sred[w][k] = part[k];
    }
    __syncthreads();

    float a2[NLOC], mx = -1e30f;
    #pragma unroll
    for (int k = 0; k < NLOC; ++k) {
        float s = (sred[0][k] + sred[1][k] + sred[2][k] + sred[3][k]) * 0.0625f;
        a2[k] = s;
        mx = fmaxf(mx, s);
    }
    float se = 0.f;
    #pragma unroll
    for (int k = 0; k < NLOC; ++k) { a2[k] = expf(a2[k] - mx); se += a2[k]; }
    const float inv = 1.f / se;
    const float bdr = DSWB[1];

    float4 p = {0, 0, 0, 0}, lm = {0, 0, 0, 0};
    #pragma unroll
    for (int k = 0; k < NLOC; ++k) {
        float ak = a2[k] * inv, wk = swd[k];
        p.x = fmaf(ak, lfv[k].x, p.x);  p.y = fmaf(ak, lfv[k].y, p.y);
        p.z = fmaf(ak, lfv[k].z, p.z);  p.w = fmaf(ak, lfv[k].w, p.w);
        lm.x = fmaf(wk, lfv[k].x, lm.x); lm.y = fmaf(wk, lfv[k].y, lm.y);
        lm.z = fmaf(wk, lfv[k].z, lm.z); lm.w = fmaf(wk, lfv[k].w, lm.w);
    }
    lm.x += bdr; lm.y += bdr; lm.z += bdr; lm.w += bdr;
    *(float4*)&DLFM[(size_t)b * 512 + tid * 4] = lm;

    __nv_bfloat16 h0, l0, h1, l1, h2, l2, h3, l3;
    split_bf16(p.x, h0, l0); split_bf16(p.y, h1, l1);
    split_bf16(p.z, h2, l2); split_bf16(p.w, h3, l3);
    __nv_bfloat162* ph = (__nv_bfloat162*)DPH;
    __nv_bfloat162* pl = (__nv_bfloat162*)DPL;
    const size_t i2 = ((size_t)b * 512 + tid * 4) >> 1;
    ph[i2]     = __nv_bfloat162(h0, h1);
    ph[i2 + 1] = __nv_bfloat162(h2, h3);
    pl[i2]     = __nv_bfloat162(l0, l1);
    pl[i2 + 1] = __nv_bfloat162(l2, l3);
}

// ---------------- launch ----------------
extern "C" void kernel_launch(void* const* d_in, const int* in_sizes, int n_in,
                              void* d_out, int out_size) {
    const float* g    = (const float*)d_in[0];
    const float* lf   = (const float*)d_in[1];
    const float* Wq   = (const float*)d_in[2];
    const float* bq   = (const float*)d_in[3];
    const float* Wk   = (const float*)d_in[4];
    // d_in[5] = bk: cancels in the softmax — unused
    const float* Wv   = (const float*)d_in[6];
    const float* bv   = (const float*)d_in[7];
    const float* w_dr = (const float*)d_in[8];
    const float* b_dr = (const float*)d_in[9];
    const float* Wf   = (const float*)d_in[10];
    const float* bf   = (const float*)d_in[11];
    float* out = (float*)d_out;

    cudaFuncSetAttribute(k_mma<512, 0>,  cudaFuncAttributeMaxDynamicSharedMemorySize, DYN_BYTES);
    cudaFuncSetAttribute(k_mma<1024, 1>, cudaFuncAttributeMaxDynamicSharedMemorySize, DYN_BYTES);

    k_sw<<<1, 32>>>(w_dr, b_dr);
    k_prep<<<dim3(8, 8, 3), 256>>>(Wq, Wk, Wv, Wf);
    k_const<<<1, 512>>>(bq, Wk, bv, Wf, bf);
    k_cvt_g<<<B_N * F_D / 1024, 256>>>(g);
    k_mma<512, 0><<<dim3(4, 128), 256, DYN_BYTES>>>(g, nullptr);   // U = g@M1 + c_u
    k_mid<<<B_N, 128>>>(lf, w_dr);                                 // softmax / p / lfm
    k_mma<1024, 1><<<dim3(4, 128), 256, DYN_BYTES>>>(g, out);      // relu([g|p]@W2+cz)+lfm+g
}

// round 12
// speedup vs baseline: 1.9452x; 1.9452x over previous
#include <cuda_runtime.h>
#include <cuda_fp16.h>
#include <cstdint>
#include <cstddef>

#define B_N   16384
#define F_D   512
#define H_D   256
#define NLOC  12

// ---------------- device scratch ----------------
__device__ float  DU  [B_N * F_D];        // u = g@M1 + c_u (fp32, for k_mid)
__device__ float  DLFM[B_N * F_D];        // lf_mean + b_dr
__device__ __half GF [B_N * F_D];         // g as fp16
__device__ __half DPF[B_N * F_D];         // p as fp16
__device__ __half M1TH[F_D * F_D], M1TL[F_D * F_D];         // (Wq@Wk^T)^T hi/lo : [n][k]
__device__ __half W2TH[F_D * 2 * F_D], W2TL[F_D * 2 * F_D]; // W2^T hi/lo : [n][k]
__device__ float DCU [F_D];
__device__ float DCZ [F_D];
__device__ float DSWB[2];                 // [0]=sum(w_dr), [1]=b_dr

// ---------------- PTX helpers ----------------
__device__ __forceinline__ void cpa16(unsigned int s, const void* g) {
    asm volatile("cp.async.cg.shared.global [%0], [%1], 16;\n" :: "r"(s), "l"(g));
}
__device__ __forceinline__ void cpa_commit() { asm volatile("cp.async.commit_group;\n"); }
__device__ __forceinline__ void cpa_wait0()  { asm volatile("cp.async.wait_group 0;\n"); }
__device__ __forceinline__ void cpa_wait1()  { asm volatile("cp.async.wait_group 1;\n"); }

__device__ __forceinline__ void mma_f16(float* c, uint32_t a0, uint32_t a1, uint32_t a2,
                                        uint32_t a3, uint32_t b0, uint32_t b1) {
    asm volatile(
        "mma.sync.aligned.m16n8k16.row.col.f32.f16.f16.f32 "
        "{%0,%1,%2,%3}, {%4,%5,%6,%7}, {%8,%9}, {%0,%1,%2,%3};\n"
        : "+f"(c[0]), "+f"(c[1]), "+f"(c[2]), "+f"(c[3])
        : "r"(a0), "r"(a1), "r"(a2), "r"(a3), "r"(b0), "r"(b1));
}

__device__ __forceinline__ void split_f16(float x, __half& h, __half& l) {
    h = __float2half_rn(x);
    l = __float2half_rn(x - __half2float(h));
}

// ---------------- kernel 0: scalars ----------------
__global__ void k_sw(const float* __restrict__ w_dr, const float* __restrict__ b_dr) {
    if (threadIdx.x == 0) {
        float s = 0.f;
        for (int k = 0; k < NLOC; ++k) s += w_dr[k];
        DSWB[0] = s;
        DSWB[1] = b_dr[0];
    }
}

// ---------------- kernel 1: weight prep -> transposed fp16 hi/lo ----------------
// mat 0: M1T[n][k]        = sum_h Wq[k][h] * Wk[n][h]
// mat 1: W2T[n][k], k<512 = Sw * sum_h Wv[k][h] * Wf[256+h][n]   (multiplies g)
// mat 2: W2T[n][512+k]    =      sum_h Wv[k][h] * Wf[h][n]       (multiplies p)
__global__ __launch_bounds__(256) void k_prep(const float* __restrict__ Wq,
                                              const float* __restrict__ Wk,
                                              const float* __restrict__ Wv,
                                              const float* __restrict__ Wf) {
    __shared__ float As[16][68];
    __shared__ float Bs[16][68];
    const int tid = threadIdx.x;
    const int tx = tid & 15, ty = tid >> 4;
    const int m0 = blockIdx.y * 64, n0 = blockIdx.x * 64, mat = blockIdx.z;
    const float* A = (mat == 0) ? Wq : Wv;
    float acc[4][4];
    #pragma unroll
    for (int i = 0; i < 4; ++i)
        #pragma unroll
        for (int j = 0; j < 4; ++j) acc[i][j] = 0.f;

    for (int kk = 0; kk < 256; kk += 16) {
        {
            int m = tid >> 2, kq = (tid & 3) * 4;
            float4 v = *(const float4*)&A[(m0 + m) * 256 + kk + kq];
            As[kq + 0][m] = v.x; As[kq + 1][m] = v.y; As[kq + 2][m] = v.z; As[kq + 3][m] = v.w;
        }
        if (mat == 0) {
            int n = tid >> 2, kq = (tid & 3) * 4;
            float4 v = *(const float4*)&Wk[(n0 + n) * 256 + kk + kq];
            Bs[kq + 0][n] = v.x; Bs[kq + 1][n] = v.y; Bs[kq + 2][n] = v.z; Bs[kq + 3][n] = v.w;
        } else {
            int kr = tid >> 4, nq = (tid & 15) * 4;
            int off = (mat == 1) ? 256 : 0;
            float4 v = *(const float4*)&Wf[(off + kk + kr) * 512 + n0 + nq];
            *(float4*)&Bs[kr][nq] = v;
        }
        __syncthreads();
        #pragma unroll
        for (int k = 0; k < 16; ++k) {
            float4 a = *(const float4*)&As[k][ty * 4];
            float4 b = *(const float4*)&Bs[k][tx * 4];
            float av[4] = {a.x, a.y, a.z, a.w};
            float bv[4] = {b.x, b.y, b.z, b.w};
            #pragma unroll
            for (int i = 0; i < 4; ++i)
                #pragma unroll
                for (int j = 0; j < 4; ++j) acc[i][j] = fmaf(av[i], bv[j], acc[i][j]);
        }
        __syncthreads();
    }
    const float sw = DSWB[0];
    #pragma unroll
    for (int i = 0; i < 4; ++i) {
        int m = m0 + ty * 4 + i;            // k index of the big GEMM
        #pragma unroll
        for (int j = 0; j < 4; ++j) {
            int n = n0 + tx * 4 + j;        // output col
            float v = acc[i][j];
            __half h, l;
            if (mat == 0) {
                split_f16(v, h, l);
                M1TH[n * 512 + m] = h; M1TL[n * 512 + m] = l;
            } else if (mat == 1) {
                split_f16(v * sw, h, l);
                W2TH[n * 1024 + m] = h; W2TL[n * 1024 + m] = l;
            } else {
                split_f16(v, h, l);
                W2TH[n * 1024 + 512 + m] = h; W2TL[n * 1024 + 512 + m] = l;
            }
        }
    }
}

// ---------------- kernel 2: constant vectors ----------------
__global__ void k_const(const float* __restrict__ bq, const float* __restrict__ Wk,
                        const float* __restrict__ bv, const float* __restrict__ Wf,
                        const float* __restrict__ bf) {
    const int o = threadIdx.x;   // 512 threads
    const float sw = DSWB[0], bdr = DSWB[1];
    float cu = 0.f;
    for (int h = 0; h < 256; ++h) cu = fmaf(bq[h], Wk[o * 256 + h], cu);
    DCU[o] = cu;
    float cz = bf[o];
    for (int h = 0; h < 256; ++h) {
        cz = fmaf(bv[h], Wf[h * 512 + o], cz);
        cz = fmaf(fmaf(sw, bv[h], bdr), Wf[(256 + h) * 512 + o], cz);
    }
    DCZ[o] = cz;
}

// ---------------- kernel 3: g -> fp16 ----------------
__global__ __launch_bounds__(256) void k_cvt_g(const float* __restrict__ g) {
    const size_t i = (size_t)blockIdx.x * 256 + threadIdx.x;   // float4 index
    float4 v = *(const float4*)&g[i * 4];
    __half2* ph = (__half2*)GF;
    ph[i * 2]     = __floats2half2_rn(v.x, v.y);
    ph[i * 2 + 1] = __floats2half2_rn(v.z, v.w);
}

// ---------------- warp-MMA fp16 2-term GEMM, depth-2 pipeline, 2 CTAs/SM ----------------
// D[m][n] = sum_k A[m][k]*BT[n][k];  CTA 128x128, 8 warps (2x4), warp 64x32.
// KB=512:  A = GF, BT = M1T(h/l);  MODE 0: DU = D + DCU
// KB=1024: A = [GF|DPF], BT = W2T(h/l); MODE 1: out = relu(D+DCZ)+DLFM+g
#define KC      32
#define SP      40                        // smem row stride (fp16 elems): 80B, conflict-free
#define SPLIT_E (128 * SP)                // 5120 elems per part per stage
#define STAGE_E (3 * SPLIT_E)             // A | Bh | Bl
#define DYN_BYTES (2 * STAGE_E * 2)       // 61440

template<int KB, int MODE>
__global__ __launch_bounds__(256, 2) void k_mma(const float* __restrict__ G,
                                                float* __restrict__ Out) {
    extern __shared__ __half smb[];
    const int tid    = threadIdx.x;
    const int lane   = tid & 31;
    const int wid    = tid >> 5;
    const int gid    = lane >> 2;          // group id 0..7
    const int tig    = lane & 3;           // thread in group
    const int warp_m = wid >> 2;           // 0..1
    const int warp_n = wid & 3;            // 0..3
    const int n0     = blockIdx.x * 128;
    const int row0   = blockIdx.y * 128;
    const int NC     = KB / KC;

    const __half* BTH = (KB == 512) ? M1TH : W2TH;
    const __half* BTL = (KB == 512) ? M1TL : W2TL;

    const uint32_t smem0 = (uint32_t)__cvta_generic_to_shared(smb);

    // load one K-chunk: A [128 x 32] + Bh/Bl [128 x 32]  (16B cp.async x 1536)
    auto load_chunk = [&](int buf, int kk) {
        const uint32_t bb = smem0 + (uint32_t)buf * (STAGE_E * 2);
        #pragma unroll
        for (int it = 0; it < 6; ++it) {
            const int q    = tid + it * 256;          // 0..1535
            const int part = q >> 9;                  // 0 A, 1 Bh, 2 Bl
            const int idx  = q & 511;
            const int row  = idx >> 2;
            const int seg  = idx & 3;                 // 16B segment (8 elems)
            const uint32_t soff = bb + (uint32_t)(part * SPLIT_E + row * SP + seg * 8) * 2;
            const __half* gp;
            if (part == 0) {
                int k = kk + seg * 8;
                const __half* src = GF;
                if (KB == 1024 && k >= 512) { src = DPF; k -= 512; }
                gp = src + (size_t)(row0 + row) * 512 + k;
            } else {
                const __half* src = (part == 1) ? BTH : BTL;
                gp = src + (size_t)(n0 + row) * KB + kk + seg * 8;
            }
            cpa16(soff, gp);
        }
        cpa_commit();
    };

    float acc[4][4][4];
    #pragma unroll
    for (int i = 0; i < 4; ++i)
        #pragma unroll
        for (int j = 0; j < 4; ++j)
            #pragma unroll
            for (int t = 0; t < 4; ++t) acc[i][j][t] = 0.f;

    load_chunk(0, 0);

    for (int c = 0; c < NC; ++c) {
        if (c + 1 < NC) { load_chunk((c + 1) & 1, (c + 1) * KC); cpa_wait1(); }
        else            { cpa_wait0(); }
        __syncthreads();

        const __half* st  = smb + (c & 1) * STAGE_E;
        const __half* pA  = st;
        const __half* pBh = st + SPLIT_E;
        const __half* pBl = st + 2 * SPLIT_E;

        #pragma unroll
        for (int ks = 0; ks < 2; ++ks) {
            const int kb = ks * 16;
            uint32_t a[4][4], bh[4][2], bl[4][2];
            #pragma unroll
            for (int mt = 0; mt < 4; ++mt) {
                const int r = warp_m * 64 + mt * 16 + gid;
                a[mt][0] = *(const uint32_t*)&pA[(r)     * SP + kb + tig * 2];
                a[mt][1] = *(const uint32_t*)&pA[(r + 8) * SP + kb + tig * 2];
                a[mt][2] = *(const uint32_t*)&pA[(r)     * SP + kb + 8 + tig * 2];
                a[mt][3] = *(const uint32_t*)&pA[(r + 8) * SP + kb + 8 + tig * 2];
            }
            #pragma unroll
            for (int nt = 0; nt < 4; ++nt) {
                const int nr = warp_n * 32 + nt * 8 + gid;
                bh[nt][0] = *(const uint32_t*)&pBh[nr * SP + kb + tig * 2];
                bh[nt][1] = *(const uint32_t*)&pBh[nr * SP + kb + 8 + tig * 2];
                bl[nt][0] = *(const uint32_t*)&pBl[nr * SP + kb + tig * 2];
                bl[nt][1] = *(const uint32_t*)&pBl[nr * SP + kb + 8 + tig * 2];
            }
            #pragma unroll
            for (int mt = 0; mt < 4; ++mt)
                #pragma unroll
                for (int nt = 0; nt < 4; ++nt) {
                    mma_f16(acc[mt][nt], a[mt][0], a[mt][1], a[mt][2], a[mt][3],
                            bh[nt][0], bh[nt][1]);
                    mma_f16(acc[mt][nt], a[mt][0], a[mt][1], a[mt][2], a[mt][3],
                            bl[nt][0], bl[nt][1]);
                }
        }
        __syncthreads();
    }

    // ---- epilogue ----
    #pragma unroll
    for (int mt = 0; mt < 4; ++mt) {
        #pragma unroll
        for (int nt = 0; nt < 4; ++nt) {
            const int col = n0 + warp_n * 32 + nt * 8 + tig * 2;
            #pragma unroll
            for (int half = 0; half < 2; ++half) {
                const int row = row0 + warp_m * 64 + mt * 16 + gid + half * 8;
                const float v0 = acc[mt][nt][half * 2 + 0];
                const float v1 = acc[mt][nt][half * 2 + 1];
                float2 o;
                if (MODE == 0) {
                    o.x = v0 + DCU[col];
                    o.y = v1 + DCU[col + 1];
                    *(float2*)&DU[(size_t)row * 512 + col] = o;
                } else {
                    float2 lm = *(const float2*)&DLFM[(size_t)row * 512 + col];
                    float2 g2 = *(const float2*)&G[(size_t)row * 512 + col];
                    o.x = fmaxf(v0 + DCZ[col],     0.f) + lm.x + g2.x;
                    o.y = fmaxf(v1 + DCZ[col + 1], 0.f) + lm.y + g2.y;
                    *(float2*)&Out[(size_t)row * 512 + col] = o;
                }
            }
        }
    }
}

// ---------------- middle kernel: softmax over 12 local tokens ----------------
__global__ __launch_bounds__(128) void k_mid(const float* __restrict__ lf,
                                             const float* __restrict__ w_dr) {
    __shared__ float sred[4][NLOC];
    __shared__ float swd[NLOC];
    const int b = blockIdx.x, tid = threadIdx.x;
    const int lane = tid & 31, w = tid >> 5;
    if (tid < NLOC) swd[tid] = w_dr[tid];

    float4 u4 = *(const float4*)&DU[(size_t)b * 512 + tid * 4];
    const float* base = lf + (size_t)b * NLOC * 512 + tid * 4;
    float4 lfv[NLOC];
    float part[NLOC];
    #pragma unroll
    for (int k = 0; k < NLOC; ++k) {
        lfv[k] = *(const float4*)&base[k * 512];
        part[k] = lfv[k].x * u4.x + lfv[k].y * u4.y + lfv[k].z * u4.z + lfv[k].w * u4.w;
    }
    #pragma unroll
    for (int k = 0; k < NLOC; ++k) {
        #pragma unroll
        for (int off = 16; off > 0; off >>= 1)
            part[k] += __shfl_xor_sync(0xffffffffu, part[k], off);
    }
    if (lane == 0) {
        #pragma unroll
        for (int k = 0; k < NLOC; ++k) sred[w][k] = part[k];
    }
    __syncthreads();

    float a2[NLOC], mx = -1e30f;
    #pragma unroll
    for (int k = 0; k < NLOC; ++k) {
        float s = (sred[0][k] + sred[1][k] + sred[2][k] + sred[3][k]) * 0.0625f;
        a2[k] = s;
        mx = fmaxf(mx, s);
    }
    float se = 0.f;
    #pragma unroll
    for (int k = 0; k < NLOC; ++k) { a2[k] = expf(a2[k] - mx); se += a2[k]; }
    const float inv = 1.f / se;
    const float bdr = DSWB[1];

    float4 p = {0, 0, 0, 0}, lm = {0, 0, 0, 0};
    #pragma unroll
    for (int k = 0; k < NLOC; ++k) {
        float ak = a2[k] * inv, wk = swd[k];
        p.x = fmaf(ak, lfv[k].x, p.x);  p.y = fmaf(ak, lfv[k].y, p.y);
        p.z = fmaf(ak, lfv[k].z, p.z);  p.w = fmaf(ak, lfv[k].w, p.w);
        lm.x = fmaf(wk, lfv[k].x, lm.x); lm.y = fmaf(wk, lfv[k].y, lm.y);
        lm.z = fmaf(wk, lfv[k].z, lm.z); lm.w = fmaf(wk, lfv[k].w, lm.w);
    }
    lm.x += bdr; lm.y += bdr; lm.z += bdr; lm.w += bdr;
    *(float4*)&DLFM[(size_t)b * 512 + tid * 4] = lm;

    __half2* ph = (__half2*)DPF;
    const size_t i2 = ((size_t)b * 512 + tid * 4) >> 1;
    ph[i2]     = __floats2half2_rn(p.x, p.y);
    ph[i2 + 1] = __floats2half2_rn(p.z, p.w);
}

// ---------------- launch ----------------
extern "C" void kernel_launch(void* const* d_in, const int* in_sizes, int n_in,
                              void* d_out, int out_size) {
    const float* g    = (const float*)d_in[0];
    const float* lf   = (const float*)d_in[1];
    const float* Wq   = (const float*)d_in[2];
    const float* bq   = (const float*)d_in[3];
    const float* Wk   = (const float*)d_in[4];
    // d_in[5] = bk: cancels in the softmax — unused
    const float* Wv   = (const float*)d_in[6];
    const float* bv   = (const float*)d_in[7];
    const float* w_dr = (const float*)d_in[8];
    const float* b_dr = (const float*)d_in[9];
    const float* Wf   = (const float*)d_in[10];
    const float* bf   = (const float*)d_in[11];
    float* out = (float*)d_out;

    cudaFuncSetAttribute(k_mma<512, 0>,  cudaFuncAttributeMaxDynamicSharedMemorySize, DYN_BYTES);
    cudaFuncSetAttribute(k_mma<1024, 1>, cudaFuncAttributeMaxDynamicSharedMemorySize, DYN_BYTES);

    k_sw<<<1, 32>>>(w_dr, b_dr);
    k_prep<<<dim3(8, 8, 3), 256>>>(Wq, Wk, Wv, Wf);
    k_const<<<1, 512>>>(bq, Wk, bv, Wf, bf);
    k_cvt_g<<<B_N * F_D / 1024, 256>>>(g);
    k_mma<512, 0><<<dim3(4, 128), 256, DYN_BYTES>>>(g, nullptr);   // U = g@M1 + c_u
    k_mid<<<B_N, 128>>>(lf, w_dr);                                 // softmax / p / lfm
    k_mma<1024, 1><<<dim3(4, 128), 256, DYN_BYTES>>>(g, out);      // relu([g|p]@W2+cz)+lfm+g
}

// round 14
// speedup vs baseline: 2.3065x; 1.1857x over previous
#include <cuda_runtime.h>
#include <cuda_fp16.h>
#include <cstdint>
#include <cstddef>

#define B_N   16384
#define F_D   512
#define H_D   256
#define NLOC  12

// ---------------- device scratch ----------------
__device__ __half DUH [B_N * F_D];        // u = g@M1 + c_u (fp16; only feeds softmax logits)
__device__ float  DLFM[B_N * F_D];        // lf_mean + b_dr
__device__ __half GF [B_N * F_D];         // g as fp16
__device__ __half DPF[B_N * F_D];         // p as fp16
__device__ __half M1T[F_D * F_D];         // (Wq@Wk^T)^T : [n][k]
__device__ __half W2T[F_D * 2 * F_D];     // W2^T : [n][k]
__device__ float DCU [F_D];
__device__ float DCZ [F_D];
__device__ float DSWB[2];                 // [0]=sum(w_dr), [1]=b_dr

// ---------------- PTX helpers ----------------
__device__ __forceinline__ void cpa16(unsigned int s, const void* g) {
    asm volatile("cp.async.cg.shared.global [%0], [%1], 16;\n" :: "r"(s), "l"(g));
}
__device__ __forceinline__ void cpa_commit() { asm volatile("cp.async.commit_group;\n"); }
__device__ __forceinline__ void cpa_wait0()  { asm volatile("cp.async.wait_group 0;\n"); }
__device__ __forceinline__ void cpa_wait1()  { asm volatile("cp.async.wait_group 1;\n"); }

__device__ __forceinline__ void mma_f16(float* c, uint32_t a0, uint32_t a1, uint32_t a2,
                                        uint32_t a3, uint32_t b0, uint32_t b1) {
    asm volatile(
        "mma.sync.aligned.m16n8k16.row.col.f32.f16.f16.f32 "
        "{%0,%1,%2,%3}, {%4,%5,%6,%7}, {%8,%9}, {%0,%1,%2,%3};\n"
        : "+f"(c[0]), "+f"(c[1]), "+f"(c[2]), "+f"(c[3])
        : "r"(a0), "r"(a1), "r"(a2), "r"(a3), "r"(b0), "r"(b1));
}

// ---------------- kernel 0: scalars ----------------
__global__ void k_sw(const float* __restrict__ w_dr, const float* __restrict__ b_dr) {
    if (threadIdx.x == 0) {
        float s = 0.f;
        for (int k = 0; k < NLOC; ++k) s += w_dr[k];
        DSWB[0] = s;
        DSWB[1] = b_dr[0];
    }
}

// ---------------- kernel 1: weight prep -> transposed fp16 ----------------
// mat 0: M1T[n][k]        = sum_h Wq[k][h] * Wk[n][h]
// mat 1: W2T[n][k], k<512 = Sw * sum_h Wv[k][h] * Wf[256+h][n]   (multiplies g)
// mat 2: W2T[n][512+k]    =      sum_h Wv[k][h] * Wf[h][n]       (multiplies p)
__global__ __launch_bounds__(256) void k_prep(const float* __restrict__ Wq,
                                              const float* __restrict__ Wk,
                                              const float* __restrict__ Wv,
                                              const float* __restrict__ Wf) {
    __shared__ float As[16][68];
    __shared__ float Bs[16][68];
    const int tid = threadIdx.x;
    const int tx = tid & 15, ty = tid >> 4;
    const int m0 = blockIdx.y * 64, n0 = blockIdx.x * 64, mat = blockIdx.z;
    const float* A = (mat == 0) ? Wq : Wv;
    float acc[4][4];
    #pragma unroll
    for (int i = 0; i < 4; ++i)
        #pragma unroll
        for (int j = 0; j < 4; ++j) acc[i][j] = 0.f;

    for (int kk = 0; kk < 256; kk += 16) {
        {
            int m = tid >> 2, kq = (tid & 3) * 4;
            float4 v = *(const float4*)&A[(m0 + m) * 256 + kk + kq];
            As[kq + 0][m] = v.x; As[kq + 1][m] = v.y; As[kq + 2][m] = v.z; As[kq + 3][m] = v.w;
        }
        if (mat == 0) {
            int n = tid >> 2, kq = (tid & 3) * 4;
            float4 v = *(const float4*)&Wk[(n0 + n) * 256 + kk + kq];
            Bs[kq + 0][n] = v.x; Bs[kq + 1][n] = v.y; Bs[kq + 2][n] = v.z; Bs[kq + 3][n] = v.w;
        } else {
            int kr = tid >> 4, nq = (tid & 15) * 4;
            int off = (mat == 1) ? 256 : 0;
            float4 v = *(const float4*)&Wf[(off + kk + kr) * 512 + n0 + nq];
            *(float4*)&Bs[kr][nq] = v;
        }
        __syncthreads();
        #pragma unroll
        for (int k = 0; k < 16; ++k) {
            float4 a = *(const float4*)&As[k][ty * 4];
            float4 b = *(const float4*)&Bs[k][tx * 4];
            float av[4] = {a.x, a.y, a.z, a.w};
            float bv[4] = {b.x, b.y, b.z, b.w};
            #pragma unroll
            for (int i = 0; i < 4; ++i)
                #pragma unroll
                for (int j = 0; j < 4; ++j) acc[i][j] = fmaf(av[i], bv[j], acc[i][j]);
        }
        __syncthreads();
    }
    const float sw = DSWB[0];
    #pragma unroll
    for (int i = 0; i < 4; ++i) {
        int m = m0 + ty * 4 + i;            // k index of the big GEMM
        #pragma unroll
        for (int j = 0; j < 4; ++j) {
            int n = n0 + tx * 4 + j;        // output col
            float v = acc[i][j];
            if (mat == 0)      M1T[n * 512 + m]        = __float2half_rn(v);
            else if (mat == 1) W2T[n * 1024 + m]       = __float2half_rn(v * sw);
            else               W2T[n * 1024 + 512 + m] = __float2half_rn(v);
        }
    }
}

// ---------------- kernel 2: constant vectors ----------------
__global__ void k_const(const float* __restrict__ bq, const float* __restrict__ Wk,
                        const float* __restrict__ bv, const float* __restrict__ Wf,
                        const float* __restrict__ bf) {
    const int o = threadIdx.x;   // 512 threads
    const float sw = DSWB[0], bdr = DSWB[1];
    float cu = 0.f;
    for (int h = 0; h < 256; ++h) cu = fmaf(bq[h], Wk[o * 256 + h], cu);
    DCU[o] = cu;
    float cz = bf[o];
    for (int h = 0; h < 256; ++h) {
        cz = fmaf(bv[h], Wf[h * 512 + o], cz);
        cz = fmaf(fmaf(sw, bv[h], bdr), Wf[(256 + h) * 512 + o], cz);
    }
    DCZ[o] = cz;
}

// ---------------- kernel 3: g -> fp16 (4 float4 per thread for MLP) ----------------
__global__ __launch_bounds__(256) void k_cvt_g(const float* __restrict__ g) {
    const size_t i0 = ((size_t)blockIdx.x * 256 + threadIdx.x) * 4;   // float4 index
    float4 v[4];
    #pragma unroll
    for (int j = 0; j < 4; ++j) v[j] = *(const float4*)&g[(i0 + j) * 4];
    __half2* ph = (__half2*)GF;
    #pragma unroll
    for (int j = 0; j < 4; ++j) {
        ph[(i0 + j) * 2]     = __floats2half2_rn(v[j].x, v[j].y);
        ph[(i0 + j) * 2 + 1] = __floats2half2_rn(v[j].z, v[j].w);
    }
}

// ---------------- warp-MMA fp16 GEMM, depth-2 pipeline, 2 CTAs/SM ----------------
// D[m][n] = sum_k A[m][k]*BT[n][k];  CTA 128x128, 8 warps (2x4), warp 64x32.
// KB=512:  A = GF, BT = M1T;  MODE 0: DUH = fp16(D + DCU)
// KB=1024: A = [GF|DPF], BT = W2T; MODE 1: out = relu(D+DCZ)+DLFM+g
#define KC      32
#define SP      40                        // smem row stride (fp16 elems): 80B, conflict-free
#define SPLIT_E (128 * SP)                // 5120 elems per part per stage
#define STAGE_E (2 * SPLIT_E)             // A | B
#define DYN_BYTES (2 * STAGE_E * 2)       // 40960

template<int KB, int MODE>
__global__ __launch_bounds__(256, 2) void k_mma(const float* __restrict__ G,
                                                float* __restrict__ Out) {
    extern __shared__ __half smb[];
    const int tid    = threadIdx.x;
    const int lane   = tid & 31;
    const int wid    = tid >> 5;
    const int gid    = lane >> 2;          // group id 0..7
    const int tig    = lane & 3;           // thread in group
    const int warp_m = wid >> 2;           // 0..1
    const int warp_n = wid & 3;            // 0..3
    const int n0     = blockIdx.x * 128;
    const int row0   = blockIdx.y * 128;
    const int NC     = KB / KC;

    const __half* BT = (KB == 512) ? M1T : W2T;

    const uint32_t smem0 = (uint32_t)__cvta_generic_to_shared(smb);

    // load one K-chunk: A [128 x 32] + B [128 x 32]  (16B cp.async x 1024)
    auto load_chunk = [&](int buf, int kk) {
        const uint32_t bb = smem0 + (uint32_t)buf * (STAGE_E * 2);
        #pragma unroll
        for (int it = 0; it < 4; ++it) {
            const int q    = tid + it * 256;          // 0..1023
            const int part = q >> 9;                  // 0 A, 1 B
            const int idx  = q & 511;
            const int row  = idx >> 2;
            const int seg  = idx & 3;                 // 16B segment (8 elems)
            const uint32_t soff = bb + (uint32_t)(part * SPLIT_E + row * SP + seg * 8) * 2;
            const __half* gp;
            if (part == 0) {
                int k = kk + seg * 8;
                const __half* src = GF;
                if (KB == 1024 && k >= 512) { src = DPF; k -= 512; }
                gp = src + (size_t)(row0 + row) * 512 + k;
            } else {
                gp = BT + (size_t)(n0 + row) * KB + kk + seg * 8;
            }
            cpa16(soff, gp);
        }
        cpa_commit();
    };

    float acc[4][4][4];
    #pragma unroll
    for (int i = 0; i < 4; ++i)
        #pragma unroll
        for (int j = 0; j < 4; ++j)
            #pragma unroll
            for (int t = 0; t < 4; ++t) acc[i][j][t] = 0.f;

    load_chunk(0, 0);

    for (int c = 0; c < NC; ++c) {
        if (c + 1 < NC) { load_chunk((c + 1) & 1, (c + 1) * KC); cpa_wait1(); }
        else            { cpa_wait0(); }
        __syncthreads();

        const __half* st = smb + (c & 1) * STAGE_E;
        const __half* pA = st;
        const __half* pB = st + SPLIT_E;

        #pragma unroll
        for (int ks = 0; ks < 2; ++ks) {
            const int kb = ks * 16;
            uint32_t a[4][4], b[4][2];
            #pragma unroll
            for (int mt = 0; mt < 4; ++mt) {
                const int r = warp_m * 64 + mt * 16 + gid;
                a[mt][0] = *(const uint32_t*)&pA[(r)     * SP + kb + tig * 2];
                a[mt][1] = *(const uint32_t*)&pA[(r + 8) * SP + kb + tig * 2];
                a[mt][2] = *(const uint32_t*)&pA[(r)     * SP + kb + 8 + tig * 2];
                a[mt][3] = *(const uint32_t*)&pA[(r + 8) * SP + kb + 8 + tig * 2];
            }
            #pragma unroll
            for (int nt = 0; nt < 4; ++nt) {
                const int nr = warp_n * 32 + nt * 8 + gid;
                b[nt][0] = *(const uint32_t*)&pB[nr * SP + kb + tig * 2];
                b[nt][1] = *(const uint32_t*)&pB[nr * SP + kb + 8 + tig * 2];
            }
            #pragma unroll
            for (int mt = 0; mt < 4; ++mt)
                #pragma unroll
                for (int nt = 0; nt < 4; ++nt)
                    mma_f16(acc[mt][nt], a[mt][0], a[mt][1], a[mt][2], a[mt][3],
                            b[nt][0], b[nt][1]);
        }
        __syncthreads();
    }

    // ---- epilogue ----
    #pragma unroll
    for (int mt = 0; mt < 4; ++mt) {
        #pragma unroll
        for (int nt = 0; nt < 4; ++nt) {
            const int col = n0 + warp_n * 32 + nt * 8 + tig * 2;
            #pragma unroll
            for (int half = 0; half < 2; ++half) {
                const int row = row0 + warp_m * 64 + mt * 16 + gid + half * 8;
                const float v0 = acc[mt][nt][half * 2 + 0];
                const float v1 = acc[mt][nt][half * 2 + 1];
                if (MODE == 0) {
                    *(__half2*)&DUH[(size_t)row * 512 + col] =
                        __floats2half2_rn(v0 + DCU[col], v1 + DCU[col + 1]);
                } else {
                    float2 lm = *(const float2*)&DLFM[(size_t)row * 512 + col];
                    float2 g2 = *(const float2*)&G[(size_t)row * 512 + col];
                    float2 o;
                    o.x = fmaxf(v0 + DCZ[col],     0.f) + lm.x + g2.x;
                    o.y = fmaxf(v1 + DCZ[col + 1], 0.f) + lm.y + g2.y;
                    *(float2*)&Out[(size_t)row * 512 + col] = o;
                }
            }
        }
    }
}

// ---------------- middle kernel: softmax over 12 local tokens ----------------
__global__ __launch_bounds__(128) void k_mid(const float* __restrict__ lf,
                                             const float* __restrict__ w_dr) {
    __shared__ float sred[4][NLOC];
    __shared__ float swd[NLOC];
    const int b = blockIdx.x, tid = threadIdx.x;
    const int lane = tid & 31, w = tid >> 5;
    if (tid < NLOC) swd[tid] = w_dr[tid];

    const __half2* pu = (const __half2*)&DUH[(size_t)b * 512 + tid * 4];
    const __half2 u01 = pu[0], u23 = pu[1];
    const float4 u4 = {__low2float(u01), __high2float(u01),
                       __low2float(u23), __high2float(u23)};
    const float* base = lf + (size_t)b * NLOC * 512 + tid * 4;
    float4 lfv[NLOC];
    float part[NLOC];
    #pragma unroll
    for (int k = 0; k < NLOC; ++k) {
        lfv[k] = *(const float4*)&base[k * 512];
        part[k] = lfv[k].x * u4.x + lfv[k].y * u4.y + lfv[k].z * u4.z + lfv[k].w * u4.w;
    }
    #pragma unroll
    for (int k = 0; k < NLOC; ++k) {
        #pragma unroll
        for (int off = 16; off > 0; off >>= 1)
            part[k] += __shfl_xor_sync(0xffffffffu, part[k], off);
    }
    if (lane == 0) {
        #pragma unroll
        for (int k = 0; k < NLOC; ++k) sred[w][k] = part[k];
    }
    __syncthreads();

    float a2[NLOC], mx = -1e30f;
    #pragma unroll
    for (int k = 0; k < NLOC; ++k) {
        float s = (sred[0][k] + sred[1][k] + sred[2][k] + sred[3][k]) * 0.0625f;
        a2[k] = s;
        mx = fmaxf(mx, s);
    }
    float se = 0.f;
    #pragma unroll
    for (int k = 0; k < NLOC; ++k) { a2[k] = expf(a2[k] - mx); se += a2[k]; }
    const float inv = 1.f / se;
    const float bdr = DSWB[1];

    float4 p = {0, 0, 0, 0}, lm = {0, 0, 0, 0};
    #pragma unroll
    for (int k = 0; k < NLOC; ++k) {
        float ak = a2[k] * inv, wk = swd[k];
        p.x = fmaf(ak, lfv[k].x, p.x);  p.y = fmaf(ak, lfv[k].y, p.y);
        p.z = fmaf(ak, lfv[k].z, p.z);  p.w = fmaf(ak, lfv[k].w, p.w);
        lm.x = fmaf(wk, lfv[k].x, lm.x); lm.y = fmaf(wk, lfv[k].y, lm.y);
        lm.z = fmaf(wk, lfv[k].z, lm.z); lm.w = fmaf(wk, lfv[k].w, lm.w);
    }
    lm.x += bdr; lm.y += bdr; lm.z += bdr; lm.w += bdr;
    *(float4*)&DLFM[(size_t)b * 512 + tid * 4] = lm;

    __half2* ph = (__half2*)DPF;
    const size_t i2 = ((size_t)b * 512 + tid * 4) >> 1;
    ph[i2]     = __floats2half2_rn(p.x, p.y);
    ph[i2 + 1] = __floats2half2_rn(p.z, p.w);
}

// ---------------- launch ----------------
extern "C" void kernel_launch(void* const* d_in, const int* in_sizes, int n_in,
                              void* d_out, int out_size) {
    const float* g    = (const float*)d_in[0];
    const float* lf   = (const float*)d_in[1];
    const float* Wq   = (const float*)d_in[2];
    const float* bq   = (const float*)d_in[3];
    const float* Wk   = (const float*)d_in[4];
    // d_in[5] = bk: cancels in the softmax — unused
    const float* Wv   = (const float*)d_in[6];
    const float* bv   = (const float*)d_in[7];
    const float* w_dr = (const float*)d_in[8];
    const float* b_dr = (const float*)d_in[9];
    const float* Wf   = (const float*)d_in[10];
    const float* bf   = (const float*)d_in[11];
    float* out = (float*)d_out;

    cudaFuncSetAttribute(k_mma<512, 0>,  cudaFuncAttributeMaxDynamicSharedMemorySize, DYN_BYTES);
    cudaFuncSetAttribute(k_mma<1024, 1>, cudaFuncAttributeMaxDynamicSharedMemorySize, DYN_BYTES);

    k_sw<<<1, 32>>>(w_dr, b_dr);
    k_prep<<<dim3(8, 8, 3), 256>>>(Wq, Wk, Wv, Wf);
    k_const<<<1, 512>>>(bq, Wk, bv, Wf, bf);
    k_cvt_g<<<B_N * F_D / 4096, 256>>>(g);
    k_mma<512, 0><<<dim3(4, 128), 256, DYN_BYTES>>>(g, nullptr);   // U = g@M1 + c_u
    k_mid<<<B_N, 128>>>(lf, w_dr);                                 // softmax / p / lfm
    k_mma<1024, 1><<<dim3(4, 128), 256, DYN_BYTES>>>(g, out);      // relu([g|p]@W2+cz)+lfm+g
}

// round 16
// speedup vs baseline: 2.4216x; 1.0499x over previous
#include <cuda_runtime.h>
#include <cuda_fp16.h>
#include <cstdint>
#include <cstddef>

#define B_N   16384
#define F_D   512
#define H_D   256
#define NLOC  12

// ---------------- device scratch ----------------
__device__ __half DUH  [B_N * F_D];       // u = g@M1 + c_u (fp16; only feeds softmax logits)
__device__ __half DLFMH[B_N * F_D];       // lf_mean + b_dr (fp16)
__device__ __half GF [B_N * F_D];         // g as fp16
__device__ __half DPF[B_N * F_D];         // p as fp16
__device__ __half M1T[F_D * F_D];         // (Wq@Wk^T)^T : [n][k]
__device__ __half W2T[F_D * 2 * F_D];     // W2^T : [n][k]
__device__ float DCU [F_D];
__device__ float DCZ [F_D];
__device__ float DSWB[2];                 // [0]=sum(w_dr), [1]=b_dr

// ---------------- PTX helpers ----------------
__device__ __forceinline__ void cpa16(unsigned int s, const void* g) {
    asm volatile("cp.async.cg.shared.global [%0], [%1], 16;\n" :: "r"(s), "l"(g));
}
__device__ __forceinline__ void cpa_commit() { asm volatile("cp.async.commit_group;\n"); }
__device__ __forceinline__ void cpa_wait0()  { asm volatile("cp.async.wait_group 0;\n"); }
__device__ __forceinline__ void cpa_wait1()  { asm volatile("cp.async.wait_group 1;\n"); }

__device__ __forceinline__ void mma_f16(float* c, uint32_t a0, uint32_t a1, uint32_t a2,
                                        uint32_t a3, uint32_t b0, uint32_t b1) {
    asm volatile(
        "mma.sync.aligned.m16n8k16.row.col.f32.f16.f16.f32 "
        "{%0,%1,%2,%3}, {%4,%5,%6,%7}, {%8,%9}, {%0,%1,%2,%3};\n"
        : "+f"(c[0]), "+f"(c[1]), "+f"(c[2]), "+f"(c[3])
        : "r"(a0), "r"(a1), "r"(a2), "r"(a3), "r"(b0), "r"(b1));
}

// ---------------- kernel 0: scalars ----------------
__global__ void k_sw(const float* __restrict__ w_dr, const float* __restrict__ b_dr) {
    if (threadIdx.x == 0) {
        float s = 0.f;
        for (int k = 0; k < NLOC; ++k) s += w_dr[k];
        DSWB[0] = s;
        DSWB[1] = b_dr[0];
    }
}

// ---------------- kernel 1: weight prep -> transposed fp16 ----------------
// mat 0: M1T[n][k]        = sum_h Wq[k][h] * Wk[n][h]
// mat 1: W2T[n][k], k<512 = Sw * sum_h Wv[k][h] * Wf[256+h][n]   (multiplies g)
// mat 2: W2T[n][512+k]    =      sum_h Wv[k][h] * Wf[h][n]       (multiplies p)
__global__ __launch_bounds__(256) void k_prep(const float* __restrict__ Wq,
                                              const float* __restrict__ Wk,
                                              const float* __restrict__ Wv,
                                              const float* __restrict__ Wf) {
    __shared__ float As[16][68];
    __shared__ float Bs[16][68];
    const int tid = threadIdx.x;
    const int tx = tid & 15, ty = tid >> 4;
    const int m0 = blockIdx.y * 64, n0 = blockIdx.x * 64, mat = blockIdx.z;
    const float* A = (mat == 0) ? Wq : Wv;
    float acc[4][4];
    #pragma unroll
    for (int i = 0; i < 4; ++i)
        #pragma unroll
        for (int j = 0; j < 4; ++j) acc[i][j] = 0.f;

    for (int kk = 0; kk < 256; kk += 16) {
        {
            int m = tid >> 2, kq = (tid & 3) * 4;
            float4 v = *(const float4*)&A[(m0 + m) * 256 + kk + kq];
            As[kq + 0][m] = v.x; As[kq + 1][m] = v.y; As[kq + 2][m] = v.z; As[kq + 3][m] = v.w;
        }
        if (mat == 0) {
            int n = tid >> 2, kq = (tid & 3) * 4;
            float4 v = *(const float4*)&Wk[(n0 + n) * 256 + kk + kq];
            Bs[kq + 0][n] = v.x; Bs[kq + 1][n] = v.y; Bs[kq + 2][n] = v.z; Bs[kq + 3][n] = v.w;
        } else {
            int kr = tid >> 4, nq = (tid & 15) * 4;
            int off = (mat == 1) ? 256 : 0;
            float4 v = *(const float4*)&Wf[(off + kk + kr) * 512 + n0 + nq];
            *(float4*)&Bs[kr][nq] = v;
        }
        __syncthreads();
        #pragma unroll
        for (int k = 0; k < 16; ++k) {
            float4 a = *(const float4*)&As[k][ty * 4];
            float4 b = *(const float4*)&Bs[k][tx * 4];
            float av[4] = {a.x, a.y, a.z, a.w};
            float bv[4] = {b.x, b.y, b.z, b.w};
            #pragma unroll
            for (int i = 0; i < 4; ++i)
                #pragma unroll
                for (int j = 0; j < 4; ++j) acc[i][j] = fmaf(av[i], bv[j], acc[i][j]);
        }
        __syncthreads();
    }
    const float sw = DSWB[0];
    #pragma unroll
    for (int i = 0; i < 4; ++i) {
        int m = m0 + ty * 4 + i;            // k index of the big GEMM
        #pragma unroll
        for (int j = 0; j < 4; ++j) {
            int n = n0 + tx * 4 + j;        // output col
            float v = acc[i][j];
            if (mat == 0)      M1T[n * 512 + m]        = __float2half_rn(v);
            else if (mat == 1) W2T[n * 1024 + m]       = __float2half_rn(v * sw);
            else               W2T[n * 1024 + 512 + m] = __float2half_rn(v);
        }
    }
}

// ---------------- kernel 2: constant vectors ----------------
__global__ void k_const(const float* __restrict__ bq, const float* __restrict__ Wk,
                        const float* __restrict__ bv, const float* __restrict__ Wf,
                        const float* __restrict__ bf) {
    const int o = threadIdx.x;   // 512 threads
    const float sw = DSWB[0], bdr = DSWB[1];
    float cu = 0.f;
    for (int h = 0; h < 256; ++h) cu = fmaf(bq[h], Wk[o * 256 + h], cu);
    DCU[o] = cu;
    float cz = bf[o];
    for (int h = 0; h < 256; ++h) {
        cz = fmaf(bv[h], Wf[h * 512 + o], cz);
        cz = fmaf(fmaf(sw, bv[h], bdr), Wf[(256 + h) * 512 + o], cz);
    }
    DCZ[o] = cz;
}

// ---------------- kernel 3: g -> fp16 (R12 form — proven fastest) ----------------
__global__ __launch_bounds__(256) void k_cvt_g(const float* __restrict__ g) {
    const size_t i = (size_t)blockIdx.x * 256 + threadIdx.x;   // float4 index
    float4 v = *(const float4*)&g[i * 4];
    __half2* ph = (__half2*)GF;
    ph[i * 2]     = __floats2half2_rn(v.x, v.y);
    ph[i * 2 + 1] = __floats2half2_rn(v.z, v.w);
}

// ---------------- warp-MMA fp16 GEMM, KC=32, depth-2 pipeline, 2 CTAs/SM ----------------
// D[m][n] = sum_k A[m][k]*BT[n][k];  CTA 128x128, 8 warps (2x4), warp 64x32.
// KB=512:  A = GF, BT = M1T;  MODE 0: DUH = fp16(D + DCU)
// KB=1024: A = [GF|DPF], BT = W2T; MODE 1: out = relu(D+DCZ)+DLFMH+g
#define KC      32
#define SP      40                        // smem row stride (fp16 elems): 80B, conflict-free
#define SPLIT_E (128 * SP)                // 5120 elems per part per stage
#define STAGE_E (2 * SPLIT_E)             // A | B
#define DYN_BYTES (2 * STAGE_E * 2)       // 40960

template<int KB, int MODE>
__global__ __launch_bounds__(256, 2) void k_mma(const float* __restrict__ G,
                                                float* __restrict__ Out) {
    extern __shared__ __half smb[];
    const int tid    = threadIdx.x;
    const int lane   = tid & 31;
    const int wid    = tid >> 5;
    const int gid    = lane >> 2;          // group id 0..7
    const int tig    = lane & 3;           // thread in group
    const int warp_m = wid >> 2;           // 0..1
    const int warp_n = wid & 3;            // 0..3
    const int n0     = blockIdx.x * 128;
    const int row0   = blockIdx.y * 128;
    const int NC     = KB / KC;

    const __half* BT = (KB == 512) ? M1T : W2T;

    const uint32_t smem0 = (uint32_t)__cvta_generic_to_shared(smb);

    // load one K-chunk: A [128 x 32] + B [128 x 32]  (16B cp.async x 1024)
    auto load_chunk = [&](int buf, int kk) {
        const uint32_t bb = smem0 + (uint32_t)buf * (STAGE_E * 2);
        #pragma unroll
        for (int it = 0; it < 4; ++it) {
            const int q    = tid + it * 256;          // 0..1023
            const int part = q >> 9;                  // 0 A, 1 B
            const int idx  = q & 511;
            const int row  = idx >> 2;
            const int seg  = idx & 3;                 // 16B segment (8 elems)
            const uint32_t soff = bb + (uint32_t)(part * SPLIT_E + row * SP + seg * 8) * 2;
            const __half* gp;
            if (part == 0) {
                int k = kk + seg * 8;
                const __half* src = GF;
                if (KB == 1024 && k >= 512) { src = DPF; k -= 512; }
                gp = src + (size_t)(row0 + row) * 512 + k;
            } else {
                gp = BT + (size_t)(n0 + row) * KB + kk + seg * 8;
            }
            cpa16(soff, gp);
        }
        cpa_commit();
    };

    float acc[4][4][4];
    #pragma unroll
    for (int i = 0; i < 4; ++i)
        #pragma unroll
        for (int j = 0; j < 4; ++j)
            #pragma unroll
            for (int t = 0; t < 4; ++t) acc[i][j][t] = 0.f;

    load_chunk(0, 0);

    for (int c = 0; c < NC; ++c) {
        if (c + 1 < NC) { load_chunk((c + 1) & 1, (c + 1) * KC); cpa_wait1(); }
        else            { cpa_wait0(); }
        __syncthreads();

        const __half* st = smb + (c & 1) * STAGE_E;
        const __half* pA = st;
        const __half* pB = st + SPLIT_E;

        #pragma unroll
        for (int ks = 0; ks < 2; ++ks) {
            const int kb = ks * 16;
            uint32_t a[4][4], b[4][2];
            #pragma unroll
            for (int mt = 0; mt < 4; ++mt) {
                const int r = warp_m * 64 + mt * 16 + gid;
                a[mt][0] = *(const uint32_t*)&pA[(r)     * SP + kb + tig * 2];
                a[mt][1] = *(const uint32_t*)&pA[(r + 8) * SP + kb + tig * 2];
                a[mt][2] = *(const uint32_t*)&pA[(r)     * SP + kb + 8 + tig * 2];
                a[mt][3] = *(const uint32_t*)&pA[(r + 8) * SP + kb + 8 + tig * 2];
            }
            #pragma unroll
            for (int nt = 0; nt < 4; ++nt) {
                const int nr = warp_n * 32 + nt * 8 + gid;
                b[nt][0] = *(const uint32_t*)&pB[nr * SP + kb + tig * 2];
                b[nt][1] = *(const uint32_t*)&pB[nr * SP + kb + 8 + tig * 2];
            }
            #pragma unroll
            for (int mt = 0; mt < 4; ++mt)
                #pragma unroll
                for (int nt = 0; nt < 4; ++nt)
                    mma_f16(acc[mt][nt], a[mt][0], a[mt][1], a[mt][2], a[mt][3],
                            b[nt][0], b[nt][1]);
        }
        __syncthreads();
    }

    // ---- epilogue ----
    #pragma unroll
    for (int mt = 0; mt < 4; ++mt) {
        #pragma unroll
        for (int nt = 0; nt < 4; ++nt) {
            const int col = n0 + warp_n * 32 + nt * 8 + tig * 2;
            #pragma unroll
            for (int half = 0; half < 2; ++half) {
                const int row = row0 + warp_m * 64 + mt * 16 + gid + half * 8;
                const float v0 = acc[mt][nt][half * 2 + 0];
                const float v1 = acc[mt][nt][half * 2 + 1];
                if (MODE == 0) {
                    *(__half2*)&DUH[(size_t)row * 512 + col] =
                        __floats2half2_rn(v0 + DCU[col], v1 + DCU[col + 1]);
                } else {
                    float2 lm = __half22float2(*(const __half2*)&DLFMH[(size_t)row * 512 + col]);
                    float2 g2 = *(const float2*)&G[(size_t)row * 512 + col];
                    float2 o;
                    o.x = fmaxf(v0 + DCZ[col],     0.f) + lm.x + g2.x;
                    o.y = fmaxf(v1 + DCZ[col + 1], 0.f) + lm.y + g2.y;
                    *(float2*)&Out[(size_t)row * 512 + col] = o;
                }
            }
        }
    }
}

// ---------------- middle kernel: softmax over 12 local tokens ----------------
__global__ __launch_bounds__(128) void k_mid(const float* __restrict__ lf,
                                             const float* __restrict__ w_dr) {
    __shared__ float sred[4][NLOC];
    __shared__ float swd[NLOC];
    const int b = blockIdx.x, tid = threadIdx.x;
    const int lane = tid & 31, w = tid >> 5;
    if (tid < NLOC) swd[tid] = w_dr[tid];

    const __half2* pu = (const __half2*)&DUH[(size_t)b * 512 + tid * 4];
    const __half2 u01 = pu[0], u23 = pu[1];
    const float4 u4 = {__low2float(u01), __high2float(u01),
                       __low2float(u23), __high2float(u23)};
    const float* base = lf + (size_t)b * NLOC * 512 + tid * 4;
    float4 lfv[NLOC];
    float part[NLOC];
    #pragma unroll
    for (int k = 0; k < NLOC; ++k) {
        lfv[k] = *(const float4*)&base[k * 512];
        part[k] = lfv[k].x * u4.x + lfv[k].y * u4.y + lfv[k].z * u4.z + lfv[k].w * u4.w;
    }
    #pragma unroll
    for (int k = 0; k < NLOC; ++k) {
        #pragma unroll
        for (int off = 16; off > 0; off >>= 1)
            part[k] += __shfl_xor_sync(0xffffffffu, part[k], off);
    }
    if (lane == 0) {
        #pragma unroll
        for (int k = 0; k < NLOC; ++k) sred[w][k] = part[k];
    }
    __syncthreads();

    float a2[NLOC], mx = -1e30f;
    #pragma unroll
    for (int k = 0; k < NLOC; ++k) {
        float s = (sred[0][k] + sred[1][k] + sred[2][k] + sred[3][k]) * 0.0625f;
        a2[k] = s;
        mx = fmaxf(mx, s);
    }
    float se = 0.f;
    #pragma unroll
    for (int k = 0; k < NLOC; ++k) { a2[k] = expf(a2[k] - mx); se += a2[k]; }
    const float inv = 1.f / se;
    const float bdr = DSWB[1];

    float4 p = {0, 0, 0, 0}, lm = {0, 0, 0, 0};
    #pragma unroll
    for (int k = 0; k < NLOC; ++k) {
        float ak = a2[k] * inv, wk = swd[k];
        p.x = fmaf(ak, lfv[k].x, p.x);  p.y = fmaf(ak, lfv[k].y, p.y);
        p.z = fmaf(ak, lfv[k].z, p.z);  p.w = fmaf(ak, lfv[k].w, p.w);
        lm.x = fmaf(wk, lfv[k].x, lm.x); lm.y = fmaf(wk, lfv[k].y, lm.y);
        lm.z = fmaf(wk, lfv[k].z, lm.z); lm.w = fmaf(wk, lfv[k].w, lm.w);
    }
    lm.x += bdr; lm.y += bdr; lm.z += bdr; lm.w += bdr;

    __half2* plm = (__half2*)DLFMH;
    __half2* ph  = (__half2*)DPF;
    const size_t i2 = ((size_t)b * 512 + tid * 4) >> 1;
    plm[i2]     = __floats2half2_rn(lm.x, lm.y);
    plm[i2 + 1] = __floats2half2_rn(lm.z, lm.w);
    ph[i2]      = __floats2half2_rn(p.x, p.y);
    ph[i2 + 1]  = __floats2half2_rn(p.z, p.w);
}

// ---------------- launch ----------------
extern "C" void kernel_launch(void* const* d_in, const int* in_sizes, int n_in,
                              void* d_out, int out_size) {
    const float* g    = (const float*)d_in[0];
    const float* lf   = (const float*)d_in[1];
    const float* Wq   = (const float*)d_in[2];
    const float* bq   = (const float*)d_in[3];
    const float* Wk   = (const float*)d_in[4];
    // d_in[5] = bk: cancels in the softmax — unused
    const float* Wv   = (const float*)d_in[6];
    const float* bv   = (const float*)d_in[7];
    const float* w_dr = (const float*)d_in[8];
    const float* b_dr = (const float*)d_in[9];
    const float* Wf   = (const float*)d_in[10];
    const float* bf   = (const float*)d_in[11];
    float* out = (float*)d_out;

    cudaFuncSetAttribute(k_mma<512, 0>,  cudaFuncAttributeMaxDynamicSharedMemorySize, DYN_BYTES);
    cudaFuncSetAttribute(k_mma<1024, 1>, cudaFuncAttributeMaxDynamicSharedMemorySize, DYN_BYTES);

    k_sw<<<1, 32>>>(w_dr, b_dr);
    k_prep<<<dim3(8, 8, 3), 256>>>(Wq, Wk, Wv, Wf);
    k_const<<<1, 512>>>(bq, Wk, bv, Wf, bf);
    k_cvt_g<<<B_N * F_D / 1024, 256>>>(g);
    k_mma<512, 0><<<dim3(4, 128), 256, DYN_BYTES>>>(g, nullptr);   // U = g@M1 + c_u
    k_mid<<<B_N, 128>>>(lf, w_dr);                                 // softmax / p / lfm
    k_mma<1024, 1><<<dim3(4, 128), 256, DYN_BYTES>>>(g, out);      // relu([g|p]@W2+cz)+lfm+g
}

// round 17
// speedup vs baseline: 2.4668x; 1.0186x over previous
#include <cuda_runtime.h>
#include <cuda_fp16.h>
#include <cstdint>
#include <cstddef>

#define B_N   16384
#define F_D   512
#define H_D   256
#define NLOC  12

// ---------------- device scratch ----------------
__device__ __half DUH  [B_N * F_D];       // u = g@M1 + c_u (fp16; only feeds softmax logits)
__device__ __half DLFMH[B_N * F_D];       // lf_mean + b_dr (fp16)
__device__ __half GF [B_N * F_D];         // g as fp16
__device__ __half DPF[B_N * F_D];         // p as fp16
__device__ __half M1T[F_D * F_D];         // (Wq@Wk^T)^T : [n][k]
__device__ __half W2T[F_D * 2 * F_D];     // W2^T : [n][k]
__device__ float DCU [F_D];
__device__ float DCZ [F_D];
__device__ float DSWB[2];                 // [0]=sum(w_dr), [1]=b_dr

// ---------------- PTX helpers ----------------
__device__ __forceinline__ void cpa16(unsigned int s, const void* g) {
    asm volatile("cp.async.cg.shared.global [%0], [%1], 16;\n" :: "r"(s), "l"(g));
}
__device__ __forceinline__ void cpa_commit() { asm volatile("cp.async.commit_group;\n"); }
__device__ __forceinline__ void cpa_wait0()  { asm volatile("cp.async.wait_group 0;\n"); }
__device__ __forceinline__ void cpa_wait1()  { asm volatile("cp.async.wait_group 1;\n"); }

__device__ __forceinline__ void mma_f16(float* c, uint32_t a0, uint32_t a1, uint32_t a2,
                                        uint32_t a3, uint32_t b0, uint32_t b1) {
    asm volatile(
        "mma.sync.aligned.m16n8k16.row.col.f32.f16.f16.f32 "
        "{%0,%1,%2,%3}, {%4,%5,%6,%7}, {%8,%9}, {%0,%1,%2,%3};\n"
        : "+f"(c[0]), "+f"(c[1]), "+f"(c[2]), "+f"(c[3])
        : "r"(a0), "r"(a1), "r"(a2), "r"(a3), "r"(b0), "r"(b1));
}

__device__ __forceinline__ void ldsm_x4(uint32_t& r0, uint32_t& r1, uint32_t& r2,
                                        uint32_t& r3, uint32_t addr) {
    asm volatile("ldmatrix.sync.aligned.m8n8.x4.shared.b16 {%0,%1,%2,%3}, [%4];"
                 : "=r"(r0), "=r"(r1), "=r"(r2), "=r"(r3) : "r"(addr));
}

// ---------------- kernel 0: scalars ----------------
__global__ void k_sw(const float* __restrict__ w_dr, const float* __restrict__ b_dr) {
    if (threadIdx.x == 0) {
        float s = 0.f;
        for (int k = 0; k < NLOC; ++k) s += w_dr[k];
        DSWB[0] = s;
        DSWB[1] = b_dr[0];
    }
}

// ---------------- kernel 1: weight prep -> transposed fp16 ----------------
// mat 0: M1T[n][k]        = sum_h Wq[k][h] * Wk[n][h]
// mat 1: W2T[n][k], k<512 = Sw * sum_h Wv[k][h] * Wf[256+h][n]   (multiplies g)
// mat 2: W2T[n][512+k]    =      sum_h Wv[k][h] * Wf[h][n]       (multiplies p)
__global__ __launch_bounds__(256) void k_prep(const float* __restrict__ Wq,
                                              const float* __restrict__ Wk,
                                              const float* __restrict__ Wv,
                                              const float* __restrict__ Wf) {
    __shared__ float As[16][68];
    __shared__ float Bs[16][68];
    const int tid = threadIdx.x;
    const int tx = tid & 15, ty = tid >> 4;
    const int m0 = blockIdx.y * 64, n0 = blockIdx.x * 64, mat = blockIdx.z;
    const float* A = (mat == 0) ? Wq : Wv;
    float acc[4][4];
    #pragma unroll
    for (int i = 0; i < 4; ++i)
        #pragma unroll
        for (int j = 0; j < 4; ++j) acc[i][j] = 0.f;

    for (int kk = 0; kk < 256; kk += 16) {
        {
            int m = tid >> 2, kq = (tid & 3) * 4;
            float4 v = *(const float4*)&A[(m0 + m) * 256 + kk + kq];
            As[kq + 0][m] = v.x; As[kq + 1][m] = v.y; As[kq + 2][m] = v.z; As[kq + 3][m] = v.w;
        }
        if (mat == 0) {
            int n = tid >> 2, kq = (tid & 3) * 4;
            float4 v = *(const float4*)&Wk[(n0 + n) * 256 + kk + kq];
            Bs[kq + 0][n] = v.x; Bs[kq + 1][n] = v.y; Bs[kq + 2][n] = v.z; Bs[kq + 3][n] = v.w;
        } else {
            int kr = tid >> 4, nq = (tid & 15) * 4;
            int off = (mat == 1) ? 256 : 0;
            float4 v = *(const float4*)&Wf[(off + kk + kr) * 512 + n0 + nq];
            *(float4*)&Bs[kr][nq] = v;
        }
        __syncthreads();
        #pragma unroll
        for (int k = 0; k < 16; ++k) {
            float4 a = *(const float4*)&As[k][ty * 4];
            float4 b = *(const float4*)&Bs[k][tx * 4];
            float av[4] = {a.x, a.y, a.z, a.w};
            float bv[4] = {b.x, b.y, b.z, b.w};
            #pragma unroll
            for (int i = 0; i < 4; ++i)
                #pragma unroll
                for (int j = 0; j < 4; ++j) acc[i][j] = fmaf(av[i], bv[j], acc[i][j]);
        }
        __syncthreads();
    }
    const float sw = DSWB[0];
    #pragma unroll
    for (int i = 0; i < 4; ++i) {
        int m = m0 + ty * 4 + i;            // k index of the big GEMM
        #pragma unroll
        for (int j = 0; j < 4; ++j) {
            int n = n0 + tx * 4 + j;        // output col
            float v = acc[i][j];
            if (mat == 0)      M1T[n * 512 + m]        = __float2half_rn(v);
            else if (mat == 1) W2T[n * 1024 + m]       = __float2half_rn(v * sw);
            else               W2T[n * 1024 + 512 + m] = __float2half_rn(v);
        }
    }
}

// ---------------- kernel 2: constant vectors ----------------
__global__ void k_const(const float* __restrict__ bq, const float* __restrict__ Wk,
                        const float* __restrict__ bv, const float* __restrict__ Wf,
                        const float* __restrict__ bf) {
    const int o = threadIdx.x;   // 512 threads
    const float sw = DSWB[0], bdr = DSWB[1];
    float cu = 0.f;
    for (int h = 0; h < 256; ++h) cu = fmaf(bq[h], Wk[o * 256 + h], cu);
    DCU[o] = cu;
    float cz = bf[o];
    for (int h = 0; h < 256; ++h) {
        cz = fmaf(bv[h], Wf[h * 512 + o], cz);
        cz = fmaf(fmaf(sw, bv[h], bdr), Wf[(256 + h) * 512 + o], cz);
    }
    DCZ[o] = cz;
}

// ---------------- kernel 3: g -> fp16 (R12 form — proven fastest) ----------------
__global__ __launch_bounds__(256) void k_cvt_g(const float* __restrict__ g) {
    const size_t i = (size_t)blockIdx.x * 256 + threadIdx.x;   // float4 index
    float4 v = *(const float4*)&g[i * 4];
    __half2* ph = (__half2*)GF;
    ph[i * 2]     = __floats2half2_rn(v.x, v.y);
    ph[i * 2 + 1] = __floats2half2_rn(v.z, v.w);
}

// ---------------- warp-MMA fp16 GEMM, KC=32, ldmatrix frags, 2 CTAs/SM ----------------
// D[m][n] = sum_k A[m][k]*BT[n][k];  CTA 128x128, 8 warps (2x4), warp 64x32.
// KB=512:  A = GF, BT = M1T;  MODE 0: DUH = fp16(D + DCU)
// KB=1024: A = [GF|DPF], BT = W2T; MODE 1: out = relu(D+DCZ)+DLFMH+g
#define KC      32
#define SP      40                        // smem row stride (fp16 elems): 80B, conflict-free
#define SPLIT_E (128 * SP)                // 5120 elems per part per stage
#define STAGE_E (2 * SPLIT_E)             // A | B
#define DYN_BYTES (2 * STAGE_E * 2)       // 40960

template<int KB, int MODE>
__global__ __launch_bounds__(256, 2) void k_mma(const float* __restrict__ G,
                                                float* __restrict__ Out) {
    extern __shared__ __half smb[];
    const int tid    = threadIdx.x;
    const int lane   = tid & 31;
    const int wid    = tid >> 5;
    const int gid    = lane >> 2;          // group id 0..7
    const int tig    = lane & 3;           // thread in group
    const int warp_m = wid >> 2;           // 0..1
    const int warp_n = wid & 3;            // 0..3
    const int n0     = blockIdx.x * 128;
    const int row0   = blockIdx.y * 128;
    const int NC     = KB / KC;

    const __half* BT = (KB == 512) ? M1T : W2T;

    const uint32_t smem0 = (uint32_t)__cvta_generic_to_shared(smb);

    // ldmatrix per-lane offsets (in halfs), relative to stage base:
    //  A x4 per mt: tiles (r..r+7,kb) (r+8..,kb) (r..,kb+8) (r+8..,kb+8)
    //    lane row = warp_m*64 + mt*16 + (lane&15); lane colseg = (lane>>4)*8
    //  B x4 per nt-pair: tiles (nt0,c0)(nt0,c1)(nt1,c0)(nt1,c1)
    //    lane row = warp_n*32 + ntp*16 + (lane&7) + ((lane>>4)<<3); colseg = ((lane>>3)&1)*8
    const uint32_t aOff = (uint32_t)((warp_m * 64 + (lane & 15)) * SP + (lane >> 4) * 8);
    const uint32_t bOff = (uint32_t)((warp_n * 32 + (lane & 7) + ((lane >> 4) << 3)) * SP
                                     + ((lane >> 3) & 1) * 8);

    // load one K-chunk: A [128 x 32] + B [128 x 32]  (16B cp.async x 1024)
    auto load_chunk = [&](int buf, int kk) {
        const uint32_t bb = smem0 + (uint32_t)buf * (STAGE_E * 2);
        #pragma unroll
        for (int it = 0; it < 4; ++it) {
            const int q    = tid + it * 256;          // 0..1023
            const int part = q >> 9;                  // 0 A, 1 B
            const int idx  = q & 511;
            const int row  = idx >> 2;
            const int seg  = idx & 3;                 // 16B segment (8 elems)
            const uint32_t soff = bb + (uint32_t)(part * SPLIT_E + row * SP + seg * 8) * 2;
            const __half* gp;
            if (part == 0) {
                int k = kk + seg * 8;
                const __half* src = GF;
                if (KB == 1024 && k >= 512) { src = DPF; k -= 512; }
                gp = src + (size_t)(row0 + row) * 512 + k;
            } else {
                gp = BT + (size_t)(n0 + row) * KB + kk + seg * 8;
            }
            cpa16(soff, gp);
        }
        cpa_commit();
    };

    float acc[4][4][4];
    #pragma unroll
    for (int i = 0; i < 4; ++i)
        #pragma unroll
        for (int j = 0; j < 4; ++j)
            #pragma unroll
            for (int t = 0; t < 4; ++t) acc[i][j][t] = 0.f;

    load_chunk(0, 0);

    for (int c = 0; c < NC; ++c) {
        if (c + 1 < NC) { load_chunk((c + 1) & 1, (c + 1) * KC); cpa_wait1(); }
        else            { cpa_wait0(); }
        __syncthreads();

        const uint32_t stA = smem0 + (uint32_t)(c & 1) * (STAGE_E * 2);
        const uint32_t stB = stA + SPLIT_E * 2;

        #pragma unroll
        for (int ks = 0; ks < 2; ++ks) {
            const uint32_t kb = ks * 16;
            uint32_t a[4][4], b[4][2];
            #pragma unroll
            for (int mt = 0; mt < 4; ++mt)
                ldsm_x4(a[mt][0], a[mt][1], a[mt][2], a[mt][3],
                        stA + (aOff + mt * 16 * SP + kb) * 2);
            #pragma unroll
            for (int ntp = 0; ntp < 2; ++ntp)
                ldsm_x4(b[ntp * 2][0], b[ntp * 2][1], b[ntp * 2 + 1][0], b[ntp * 2 + 1][1],
                        stB + (bOff + ntp * 16 * SP + kb) * 2);
            #pragma unroll
            for (int mt = 0; mt < 4; ++mt)
                #pragma unroll
                for (int nt = 0; nt < 4; ++nt)
                    mma_f16(acc[mt][nt], a[mt][0], a[mt][1], a[mt][2], a[mt][3],
                            b[nt][0], b[nt][1]);
        }
        __syncthreads();
    }

    // ---- epilogue ----
    #pragma unroll
    for (int mt = 0; mt < 4; ++mt) {
        #pragma unroll
        for (int nt = 0; nt < 4; ++nt) {
            const int col = n0 + warp_n * 32 + nt * 8 + tig * 2;
            #pragma unroll
            for (int half = 0; half < 2; ++half) {
                const int row = row0 + warp_m * 64 + mt * 16 + gid + half * 8;
                const float v0 = acc[mt][nt][half * 2 + 0];
                const float v1 = acc[mt][nt][half * 2 + 1];
                if (MODE == 0) {
                    *(__half2*)&DUH[(size_t)row * 512 + col] =
                        __floats2half2_rn(v0 + DCU[col], v1 + DCU[col + 1]);
                } else {
                    float2 lm = __half22float2(*(const __half2*)&DLFMH[(size_t)row * 512 + col]);
                    float2 g2 = *(const float2*)&G[(size_t)row * 512 + col];
                    float2 o;
                    o.x = fmaxf(v0 + DCZ[col],     0.f) + lm.x + g2.x;
                    o.y = fmaxf(v1 + DCZ[col + 1], 0.f) + lm.y + g2.y;
                    *(float2*)&Out[(size_t)row * 512 + col] = o;
                }
            }
        }
    }
}

// ---------------- middle kernel: softmax over 12 local tokens ----------------
__global__ __launch_bounds__(128) void k_mid(const float* __restrict__ lf,
                                             const float* __restrict__ w_dr) {
    __shared__ float sred[4][NLOC];
    __shared__ float swd[NLOC];
    const int b = blockIdx.x, tid = threadIdx.x;
    const int lane = tid & 31, w = tid >> 5;
    if (tid < NLOC) swd[tid] = w_dr[tid];

    const __half2* pu = (const __half2*)&DUH[(size_t)b * 512 + tid * 4];
    const __half2 u01 = pu[0], u23 = pu[1];
    const float4 u4 = {__low2float(u01), __high2float(u01),
                       __low2float(u23), __high2float(u23)};
    const float* base = lf + (size_t)b * NLOC * 512 + tid * 4;
    float4 lfv[NLOC];
    float part[NLOC];
    #pragma unroll
    for (int k = 0; k < NLOC; ++k) {
        lfv[k] = *(const float4*)&base[k * 512];
        part[k] = lfv[k].x * u4.x + lfv[k].y * u4.y + lfv[k].z * u4.z + lfv[k].w * u4.w;
    }
    #pragma unroll
    for (int k = 0; k < NLOC; ++k) {
        #pragma unroll
        for (int off = 16; off > 0; off >>= 1)
            part[k] += __shfl_xor_sync(0xffffffffu, part[k], off);
    }
    if (lane == 0) {
        #pragma unroll
        for (int k = 0; k < NLOC; ++k) sred[w][k] = part[k];
    }
    __syncthreads();

    float a2[NLOC], mx = -1e30f;
    #pragma unroll
    for (int k = 0; k < NLOC; ++k) {
        float s = (sred[0][k] + sred[1][k] + sred[2][k] + sred[3][k]) * 0.0625f;
        a2[k] = s;
        mx = fmaxf(mx, s);
    }
    float se = 0.f;
    #pragma unroll
    for (int k = 0; k < NLOC; ++k) { a2[k] = expf(a2[k] - mx); se += a2[k]; }
    const float inv = 1.f / se;
    const float bdr = DSWB[1];

    float4 p = {0, 0, 0, 0}, lm = {0, 0, 0, 0};
    #pragma unroll
    for (int k = 0; k < NLOC; ++k) {
        float ak = a2[k] * inv, wk = swd[k];
        p.x = fmaf(ak, lfv[k].x, p.x);  p.y = fmaf(ak, lfv[k].y, p.y);
        p.z = fmaf(ak, lfv[k].z, p.z);  p.w = fmaf(ak, lfv[k].w, p.w);
        lm.x = fmaf(wk, lfv[k].x, lm.x); lm.y = fmaf(wk, lfv[k].y, lm.y);
        lm.z = fmaf(wk, lfv[k].z, lm.z); lm.w = fmaf(wk, lfv[k].w, lm.w);
    }
    lm.x += bdr; lm.y += bdr; lm.z += bdr; lm.w += bdr;

    __half2* plm = (__half2*)DLFMH;
    __half2* ph  = (__half2*)DPF;
    const size_t i2 = ((size_t)b * 512 + tid * 4) >> 1;
    plm[i2]     = __floats2half2_rn(lm.x, lm.y);
    plm[i2 + 1] = __floats2half2_rn(lm.z, lm.w);
    ph[i2]      = __floats2half2_rn(p.x, p.y);
    ph[i2 + 1]  = __floats2half2_rn(p.z, p.w);
}

// ---------------- launch ----------------
extern "C" void kernel_launch(void* const* d_in, const int* in_sizes, int n_in,
                              void* d_out, int out_size) {
    const float* g    = (const float*)d_in[0];
    const float* lf   = (const float*)d_in[1];
    const float* Wq   = (const float*)d_in[2];
    const float* bq   = (const float*)d_in[3];
    const float* Wk   = (const float*)d_in[4];
    // d_in[5] = bk: cancels in the softmax — unused
    const float* Wv   = (const float*)d_in[6];
    const float* bv   = (const float*)d_in[7];
    const float* w_dr = (const float*)d_in[8];
    const float* b_dr = (const float*)d_in[9];
    const float* Wf   = (const float*)d_in[10];
    const float* bf   = (const float*)d_in[11];
    float* out = (float*)d_out;

    cudaFuncSetAttribute(k_mma<512, 0>,  cudaFuncAttributeMaxDynamicSharedMemorySize, DYN_BYTES);
    cudaFuncSetAttribute(k_mma<1024, 1>, cudaFuncAttributeMaxDynamicSharedMemorySize, DYN_BYTES);

    k_sw<<<1, 32>>>(w_dr, b_dr);
    k_prep<<<dim3(8, 8, 3), 256>>>(Wq, Wk, Wv, Wf);
    k_const<<<1, 512>>>(bq, Wk, bv, Wf, bf);
    k_cvt_g<<<B_N * F_D / 1024, 256>>>(g);
    k_mma<512, 0><<<dim3(4, 128), 256, DYN_BYTES>>>(g, nullptr);   // U = g@M1 + c_u
    k_mid<<<B_N, 128>>>(lf, w_dr);                                 // softmax / p / lfm
    k_mma<1024, 1><<<dim3(4, 128), 256, DYN_BYTES>>>(g, out);      // relu([g|p]@W2+cz)+lfm+g
}